// round 15
// baseline (speedup 1.0000x reference)
#include <cuda_runtime.h>
#include <cuda_bf16.h>
#include <cstdint>

#define H 192
#define X384 384
#define NNODES 504   // 256 leaves + 128 + 64 + 32 + 16 + 8
#define NSUB 6       // k stages of 64

// Scratch (allocation-free rule: __device__ globals)
__device__ __nv_bfloat16 g_Vbf[(size_t)H * X384 * X384];  // 54 MB bf16 V
__device__ __nv_bfloat16 g_WTbf[256 * X384];              // W^T bf16, rows 192..255 zero
__device__ __nv_bfloat16 g_cB[128 * X384];                // current-level node vectors, bf16
__device__ float g_nodes[NNODES * H];
__device__ float g_part[7][H][128];                        // 6 x-block partials + Wx

// ---------------------------------------------------------------------------
// helpers
// ---------------------------------------------------------------------------
__device__ __forceinline__ void cp16(void* smem, const void* gmem) {
    unsigned s = (unsigned)__cvta_generic_to_shared(smem);
    asm volatile("cp.async.cg.shared.global [%0], [%1], 16;\n" :: "r"(s), "l"(gmem));
}
__device__ __forceinline__ void cp_commit() { asm volatile("cp.async.commit_group;\n"); }
template <int N>
__device__ __forceinline__ void cp_wait() { asm volatile("cp.async.wait_group %0;\n" :: "n"(N)); }

__device__ __forceinline__ void ldmx4(unsigned* a, unsigned saddr) {
    asm volatile("ldmatrix.sync.aligned.m8n8.x4.shared.b16 {%0,%1,%2,%3}, [%4];"
                 : "=r"(a[0]), "=r"(a[1]), "=r"(a[2]), "=r"(a[3]) : "r"(saddr));
}
__device__ __forceinline__ void ldmx2(unsigned* a, unsigned saddr) {
    asm volatile("ldmatrix.sync.aligned.m8n8.x2.shared.b16 {%0,%1}, [%2];"
                 : "=r"(a[0]), "=r"(a[1]) : "r"(saddr));
}
__device__ __forceinline__ void mma16816(float* d, const unsigned* a, unsigned b0, unsigned b1) {
    asm volatile(
        "mma.sync.aligned.m16n8k16.row.col.f32.bf16.bf16.f32 "
        "{%0,%1,%2,%3},{%4,%5,%6,%7},{%8,%9},{%0,%1,%2,%3};"
        : "+f"(d[0]), "+f"(d[1]), "+f"(d[2]), "+f"(d[3])
        : "r"(a[0]), "r"(a[1]), "r"(a[2]), "r"(a[3]), "r"(b0), "r"(b1));
}

// ---------------------------------------------------------------------------
// Kernel 1: convert Vt fp32 -> bf16
// ---------------------------------------------------------------------------
__global__ void convert_kernel(const float* __restrict__ Vt) {
    size_t t = (size_t)blockIdx.x * 256 + threadIdx.x;
    const float4* src = (const float4*)Vt;
    const size_t stride = 1728ull * 256ull;
    #pragma unroll 16
    for (int j = 0; j < 16; j++) {
        size_t i = t + stride * j;
        float4 v = src[i];
        __nv_bfloat162 lo, hi;
        lo.x = __float2bfloat16_rn(v.x); lo.y = __float2bfloat16_rn(v.y);
        hi.x = __float2bfloat16_rn(v.z); hi.y = __float2bfloat16_rn(v.w);
        uint2 pk; pk.x = *(const unsigned*)&lo; pk.y = *(const unsigned*)&hi;
        *(uint2*)(g_Vbf + 4 * i) = pk;
    }
}

// W^T bf16: g_WTbf[h][y] = W[y][h]; rows >= 192 zero
__global__ void convertWT_kernel(const float* __restrict__ W) {
    int h = blockIdx.x;
    for (int y = threadIdx.x; y < X384; y += blockDim.x)
        g_WTbf[h * X384 + y] = __float2bfloat16_rn(h < H ? W[y * H + h] : 0.f);
}

// ---------------------------------------------------------------------------
// Kernel 2: leaf embedding gather + level-0 B production
// ---------------------------------------------------------------------------
__global__ void leaf_kernel(const float* __restrict__ embed, const int* __restrict__ leaf_ids) {
    int n = blockIdx.x, t = threadIdx.x;
    float v = embed[(size_t)leaf_ids[n] * H + t];
    g_nodes[n * H + t] = v;
    int q = n & 31;
    int m = (n >> 5) * 16 + (q >> 1);
    g_cB[m * X384 + (q & 1) * H + t] = __float2bfloat16_rn(v);
}

// ---------------------------------------------------------------------------
// Level GEMM. M=64 row blocks; BOTH A and B staged along k in 3-slot rings
// (each slot: rows x 128B, chunk XOR swizzle), same commit group per stage.
//   mblk < 1152 : A = V rows (h = mblk/6, x-block = mblk%6) -> U[x,n],
//                 epilogue y[n] += sum_x c[n,x] U[x,n] -> g_part[xb][h][n]
//                 (c read from g_cB: the B ring slice may be overwritten)
//   mblk >=1152 : A = W^T rows (64 per block) -> g_part[6][h][n]
// grid = (1156, ceil(Nlev/NTILE)), 256 threads (4 m-warps x 2 n-warps).
// ---------------------------------------------------------------------------
template <int NTILE>
__global__ void __launch_bounds__(256, NTILE <= 64 ? 4 : 3)
gemm_level() {
    constexpr int NT = NTILE / 16;               // n8 tiles per n-warp (8,4,2,1)
    constexpr int NP = NT / 2;                   // ldmatrix.x4 pairs (0 when NT==1)
    constexpr int NBCH = NTILE * 8;              // B chunks per stage
    constexpr int BSTG = NTILE * 128;            // B stage bytes

    extern __shared__ char smraw[];
    char* As = smraw;                            // [3][64][128B]
    char* Bp = smraw + 3 * 8192;                 // [3][NTILE][128B]
    float* ysm = (float*)(Bp + 3 * BSTG);        // [4][NTILE]

    const int mblk = blockIdx.x;
    const int n0 = blockIdx.y * NTILE;
    const bool isW = (mblk >= 1152);
    const __nv_bfloat16* __restrict__ Ag = isW
        ? (g_WTbf + (size_t)(mblk - 1152) * 64 * X384)
        : (g_Vbf + ((size_t)(mblk / 6) * X384 + (mblk % 6) * 64) * X384);

    const int tid = threadIdx.x;
    const int ar = tid >> 3, ac = tid & 7;       // A: rows {ar, ar+32}, chunk ac

    // ---- prologue: stages 0,1 (A + B k-slice in one group each) ----
    #pragma unroll
    for (int s = 0; s < 2; s++) {
        char* Ad = As + s * 8192;
        #pragma unroll
        for (int t = 0; t < 2; t++) {
            int r = ar + t * 32;
            cp16(Ad + r * 128 + (((ac ^ (r & 7)) << 4)), Ag + r * X384 + s * 64 + ac * 8);
        }
        char* Bd = Bp + s * BSTG;
        for (int j = tid; j < NBCH; j += 256) {
            int n = j >> 3, c = j & 7;
            cp16(Bd + n * 128 + (((c ^ (n & 7)) << 4)),
                 g_cB + (size_t)(n0 + n) * X384 + s * 64 + c * 8);
        }
        cp_commit();
    }

    const int warp = tid >> 5, lane = tid & 31;
    const int wm = warp & 3, wn = warp >> 2;     // 4 m-warps x 2 n-warps
    const int g = lane >> 2, tg = lane & 3;
    const int m0 = wm * 16;
    const int nb0 = wn * (NT * 8);

    const unsigned As_u = (unsigned)__cvta_generic_to_shared(As);
    const unsigned Bs_u = (unsigned)__cvta_generic_to_shared(Bp);

    // A ldmatrix addresses (stage-relative, one per k-step)
    const int am = m0 + (lane & 15);
    unsigned a_off[4];
    #pragma unroll
    for (int ks = 0; ks < 4; ks++) {
        int c = ks * 2 + (lane >> 4);
        a_off[ks] = (unsigned)(am * 128 + ((c ^ (am & 7)) << 4));
    }

    // B ldmatrix lane geometry (stage-relative)
    const int bmm = lane >> 3, brr = lane & 7;
    const int rowo = (bmm & 2) ? 8 : 0, kos = bmm & 1;
    unsigned b_row[NP > 0 ? NP : 1];
    unsigned b_xm[NP > 0 ? NP : 1];
    #pragma unroll
    for (int p = 0; p < (NP > 0 ? NP : 1); p++) {
        int nr = nb0 + p * 16 + rowo + brr;
        b_row[p] = (unsigned)(nr * 128);
        b_xm[p] = (unsigned)(nr & 7);
    }
    const int nr1 = nb0 + brr;                   // NT==1 (x2) path
    const unsigned b_row1 = (unsigned)(nr1 * 128), b_xm1 = (unsigned)(nr1 & 7);

    float acc[NT][4];
    #pragma unroll
    for (int nt = 0; nt < NT; nt++)
        #pragma unroll
        for (int q = 0; q < 4; q++) acc[nt][q] = 0.f;

    // ---- mainloop over 6 k-stages ----
    for (int s = 0; s < NSUB; s++) {
        if (s == NSUB - 1) cp_wait<0>(); else cp_wait<1>();
        __syncthreads();
        int sn = s + 2;
        if (sn < NSUB) {                          // refill slot freed by stage s-1
            char* Ad = As + (sn % 3) * 8192;
            #pragma unroll
            for (int t = 0; t < 2; t++) {
                int r = ar + t * 32;
                cp16(Ad + r * 128 + (((ac ^ (r & 7)) << 4)), Ag + r * X384 + sn * 64 + ac * 8);
            }
            char* Bd = Bp + (sn % 3) * BSTG;
            for (int j = tid; j < NBCH; j += 256) {
                int n = j >> 3, c = j & 7;
                cp16(Bd + n * 128 + (((c ^ (n & 7)) << 4)),
                     g_cB + (size_t)(n0 + n) * X384 + sn * 64 + c * 8);
            }
            cp_commit();
        }

        const unsigned a_stg = As_u + (s % 3) * 8192;
        const unsigned b_stg = Bs_u + (s % 3) * BSTG;

        #pragma unroll
        for (int ks = 0; ks < 4; ks++) {
            unsigned a[4];
            ldmx4(a, a_stg + a_off[ks]);
            const unsigned c = (unsigned)(ks * 2 + kos);
            if constexpr (NP > 0) {
                #pragma unroll
                for (int p = 0; p < NP; p++) {
                    unsigned bb[4];
                    ldmx4(bb, b_stg + b_row[p] + ((c ^ b_xm[p]) << 4));
                    mma16816(acc[2 * p],     a, bb[0], bb[1]);
                    mma16816(acc[2 * p + 1], a, bb[2], bb[3]);
                }
            } else {
                unsigned bb[2];
                ldmx2(bb, b_stg + b_row1 + ((c ^ b_xm1) << 4));
                mma16816(acc[0], a, bb[0], bb[1]);
            }
        }
    }

    if (!isW) {
        const int xb = mblk % 6, hh = mblk / 6;
        const int xf = xb * 64 + m0 + g;          // global x for this thread's rows
        #pragma unroll
        for (int nt = 0; nt < NT; nt++) {
            int nl = nb0 + nt * 8 + 2 * tg;       // local n
            const __nv_bfloat16* c0p = g_cB + (size_t)(n0 + nl) * X384 + xf;
            const __nv_bfloat16* c1p = c0p + X384;
            float p0 = __bfloat162float(c0p[0]) * acc[nt][0]
                     + __bfloat162float(c0p[8]) * acc[nt][2];
            float p1 = __bfloat162float(c1p[0]) * acc[nt][1]
                     + __bfloat162float(c1p[8]) * acc[nt][3];
            #pragma unroll
            for (int sh = 4; sh < 32; sh <<= 1) { // reduce over g
                p0 += __shfl_xor_sync(0xffffffffu, p0, sh);
                p1 += __shfl_xor_sync(0xffffffffu, p1, sh);
            }
            if (g == 0) {
                ysm[wm * NTILE + nl] = p0;
                ysm[wm * NTILE + nl + 1] = p1;
            }
        }
        __syncthreads();
        for (int n = tid; n < NTILE; n += 256) {
            float v = ysm[n] + ysm[NTILE + n] + ysm[2 * NTILE + n] + ysm[3 * NTILE + n];
            g_part[xb][hh][n0 + n] = v;
        }
    } else {
        const int hb = (mblk - 1152) * 64;
        int hh = hb + m0 + g;
        #pragma unroll
        for (int nt = 0; nt < NT; nt++) {
            int n = n0 + nb0 + nt * 8 + 2 * tg;
            if (hh < H) {
                g_part[6][hh][n]     = acc[nt][0];
                g_part[6][hh][n + 1] = acc[nt][1];
            }
            if (hh + 8 < H) {
                g_part[6][hh + 8][n]     = acc[nt][2];
                g_part[6][hh + 8][n + 1] = acc[nt][3];
            }
        }
    }
}

// ---------------------------------------------------------------------------
// Finalize: sum partials + bias, tanh, write node + next level's B row.
// ---------------------------------------------------------------------------
__global__ void finalize_kernel(int outBase, int Nout, int hasNext,
                                const float* __restrict__ bias) {
    int n = blockIdx.x, h = threadIdx.x;
    float v = bias[h];
    #pragma unroll
    for (int i = 0; i < 7; i++) v += g_part[i][h][n];
    v = tanhf(v);
    g_nodes[(size_t)(outBase + n) * H + h] = v;
    if (hasNext) {
        int npt = Nout >> 3;
        int bt = n / npt, j = n - bt * npt;
        int m = bt * (npt >> 1) + (j >> 1);
        g_cB[m * X384 + (j & 1) * H + h] = __float2bfloat16_rn(v);
    }
}

// ---------------------------------------------------------------------------
// Logits + log_softmax, one warp per node
// ---------------------------------------------------------------------------
__global__ void logits_kernel(const float* __restrict__ Wout_w,
                              const float* __restrict__ Wout_b,
                              float* __restrict__ out) {
    int node = (blockIdx.x * blockDim.x + threadIdx.x) >> 5;   // 63 * 8 = 504
    int lane = threadIdx.x & 31;
    const float* v = g_nodes + (size_t)node * H;
    float l[5];
    #pragma unroll
    for (int o = 0; o < 5; o++) {
        float p = 0.f;
        #pragma unroll
        for (int i = 0; i < 6; i++) {
            int idx = lane + 32 * i;
            p += v[idx] * Wout_w[o * H + idx];
        }
        #pragma unroll
        for (int s = 16; s; s >>= 1) p += __shfl_xor_sync(0xffffffffu, p, s);
        l[o] = p + Wout_b[o];
    }
    if (lane == 0) {
        float m = l[0];
        #pragma unroll
        for (int o = 1; o < 5; o++) m = fmaxf(m, l[o]);
        float s = 0.f;
        #pragma unroll
        for (int o = 0; o < 5; o++) s += expf(l[o] - m);
        float ls = logf(s);
        #pragma unroll
        for (int o = 0; o < 5; o++) out[node * 5 + o] = l[o] - m - ls;
    }
}

// ---------------------------------------------------------------------------
static inline size_t smem_bytes(int NTILE) {
    return (size_t)3 * 8192 + (size_t)3 * NTILE * 128 + (size_t)4 * NTILE * 4;
}

extern "C" void kernel_launch(void* const* d_in, const int* in_sizes, int n_in,
                              void* d_out, int out_size) {
    const float* embed  = (const float*)d_in[0];
    const float* Vt     = (const float*)d_in[1];
    const float* W      = (const float*)d_in[2];
    const float* b      = (const float*)d_in[3];
    const float* Wout_w = (const float*)d_in[4];
    const float* Wout_b = (const float*)d_in[5];
    const int*   leaf   = (const int*)d_in[6];
    float* out = (float*)d_out;

    static bool attr_set = false;
    if (!attr_set) {
        cudaFuncSetAttribute(gemm_level<128>, cudaFuncAttributeMaxDynamicSharedMemorySize, (int)smem_bytes(128));
        cudaFuncSetAttribute(gemm_level<64>,  cudaFuncAttributeMaxDynamicSharedMemorySize, (int)smem_bytes(64));
        cudaFuncSetAttribute(gemm_level<32>,  cudaFuncAttributeMaxDynamicSharedMemorySize, (int)smem_bytes(32));
        cudaFuncSetAttribute(gemm_level<16>,  cudaFuncAttributeMaxDynamicSharedMemorySize, (int)smem_bytes(16));
        attr_set = true;
    }

    convert_kernel<<<1728, 256>>>(Vt);
    convertWT_kernel<<<256, 128>>>(W);
    leaf_kernel<<<256, H>>>(embed, leaf);   // also builds level-0 B

    // level 0: 256 leaves -> 128 nodes (V read ONCE: NTILE=128)
    gemm_level<128><<<dim3(1156, 1), 256, smem_bytes(128)>>>();
    finalize_kernel<<<128, H>>>(256, 128, 1, b);
    // level 1: 128 -> 64
    gemm_level<64><<<dim3(1156, 1), 256, smem_bytes(64)>>>();
    finalize_kernel<<<64, H>>>(384, 64, 1, b);
    // level 2: 64 -> 32
    gemm_level<32><<<dim3(1156, 1), 256, smem_bytes(32)>>>();
    finalize_kernel<<<32, H>>>(448, 32, 1, b);
    // level 3: 32 -> 16
    gemm_level<16><<<dim3(1156, 1), 256, smem_bytes(16)>>>();
    finalize_kernel<<<16, H>>>(480, 16, 1, b);
    // level 4: 16 -> 8 (B rows 8..15 stale but feed only unused columns)
    gemm_level<16><<<dim3(1156, 1), 256, smem_bytes(16)>>>();
    finalize_kernel<<<8, H>>>(496, 8, 0, b);

    logits_kernel<<<63, 256>>>(Wout_w, Wout_b, out);
}

// round 16
// speedup vs baseline: 1.0105x; 1.0105x over previous
#include <cuda_runtime.h>
#include <cuda_bf16.h>
#include <cstdint>

#define H 192
#define X384 384
#define NNODES 504   // 256 leaves + 128 + 64 + 32 + 16 + 8
#define NSUB 6       // k stages of 64

// Scratch (allocation-free rule: __device__ globals)
__device__ __nv_bfloat16 g_Vbf[(size_t)H * X384 * X384];  // 54 MB bf16 V (written by level 0)
__device__ __nv_bfloat16 g_WTbf[256 * X384];              // W^T bf16, rows 192..255 zero
__device__ float g_WTf32[256 * X384];                     // W^T fp32 (level-0 path), padded
__device__ __nv_bfloat16 g_cB[128 * X384];                // current-level node vectors, bf16
__device__ float g_nodes[NNODES * H];
__device__ float g_part[7][H][128];                        // 6 x-block partials + Wx

// ---------------------------------------------------------------------------
// helpers
// ---------------------------------------------------------------------------
__device__ __forceinline__ void cp16(void* smem, const void* gmem) {
    unsigned s = (unsigned)__cvta_generic_to_shared(smem);
    asm volatile("cp.async.cg.shared.global [%0], [%1], 16;\n" :: "r"(s), "l"(gmem));
}
__device__ __forceinline__ void cp_commit() { asm volatile("cp.async.commit_group;\n"); }
template <int N>
__device__ __forceinline__ void cp_wait() { asm volatile("cp.async.wait_group %0;\n" :: "n"(N)); }

__device__ __forceinline__ void ldmx4(unsigned* a, unsigned saddr) {
    asm volatile("ldmatrix.sync.aligned.m8n8.x4.shared.b16 {%0,%1,%2,%3}, [%4];"
                 : "=r"(a[0]), "=r"(a[1]), "=r"(a[2]), "=r"(a[3]) : "r"(saddr));
}
__device__ __forceinline__ void ldmx2(unsigned* a, unsigned saddr) {
    asm volatile("ldmatrix.sync.aligned.m8n8.x2.shared.b16 {%0,%1}, [%2];"
                 : "=r"(a[0]), "=r"(a[1]) : "r"(saddr));
}
__device__ __forceinline__ void mma16816(float* d, const unsigned* a, unsigned b0, unsigned b1) {
    asm volatile(
        "mma.sync.aligned.m16n8k16.row.col.f32.bf16.bf16.f32 "
        "{%0,%1,%2,%3},{%4,%5,%6,%7},{%8,%9},{%0,%1,%2,%3};"
        : "+f"(d[0]), "+f"(d[1]), "+f"(d[2]), "+f"(d[3])
        : "r"(a[0]), "r"(a[1]), "r"(a[2]), "r"(a[3]), "r"(b0), "r"(b1));
}
__device__ __forceinline__ unsigned pack_bf2(float x, float y) {
    __nv_bfloat162 t;
    t.x = __float2bfloat16_rn(x); t.y = __float2bfloat16_rn(y);
    return *(const unsigned*)&t;
}

// ---------------------------------------------------------------------------
// W^T: g_WTf32 / g_WTbf [h][y] = W[y][h]; rows >= 192 zero
// ---------------------------------------------------------------------------
__global__ void convertWT_kernel(const float* __restrict__ W) {
    int h = blockIdx.x;
    for (int y = threadIdx.x; y < X384; y += blockDim.x) {
        float v = (h < H) ? W[y * H + h] : 0.f;
        g_WTf32[h * X384 + y] = v;
        g_WTbf[h * X384 + y] = __float2bfloat16_rn(v);
    }
}

// ---------------------------------------------------------------------------
// Leaf embedding gather + level-0 B production
// ---------------------------------------------------------------------------
__global__ void leaf_kernel(const float* __restrict__ embed, const int* __restrict__ leaf_ids) {
    int n = blockIdx.x, t = threadIdx.x;
    float v = embed[(size_t)leaf_ids[n] * H + t];
    g_nodes[n * H + t] = v;
    int q = n & 31;
    int m = (n >> 5) * 16 + (q >> 1);
    g_cB[m * X384 + (q & 1) * H + t] = __float2bfloat16_rn(v);
}

// ---------------------------------------------------------------------------
// Level GEMM. M=64 row blocks.
// CONV=true (level 0): A read as fp32 from Vt (or g_WTf32), converted in-reg,
//   STS bf16 (2-slot buffer) + STG bf16 to g_Vbf (producing the bf16 V copy).
// CONV=false: A from g_Vbf/g_WTbf via cp.async 3-slot ring.
// B: always cp.async 3-slot k-ring from g_cB, one commit group per stage.
//   mblk < 1152 : A = V rows (h = mblk/6, x-block = mblk%6) -> U[x,n],
//                 epilogue y[n] += sum_x c[n,x] U[x,n] -> g_part[xb][h][n]
//   mblk >=1152 : A = W^T rows -> g_part[6][h][n]
// grid = (1156, ceil(Nlev/NTILE)), 256 threads (4 m-warps x 2 n-warps).
// ---------------------------------------------------------------------------
template <int NTILE, bool CONV>
__global__ void __launch_bounds__(256, CONV ? 2 : (NTILE <= 64 ? 4 : 3))
gemm_level(const float* __restrict__ Vt) {
    constexpr int NT = NTILE / 16;               // n8 tiles per n-warp
    constexpr int NP = NT / 2;                   // ldmatrix.x4 pairs (0 when NT==1)
    constexpr int NBCH = NTILE * 8;              // B chunks per stage
    constexpr int BSTG = NTILE * 128;            // B stage bytes
    constexpr int ASLOTS = CONV ? 2 : 3;

    extern __shared__ char smraw[];
    char* As = smraw;                            // [ASLOTS][64][128B]
    char* Bp = smraw + ASLOTS * 8192;            // [3][NTILE][128B]
    float* ysm = (float*)(Bp + 3 * BSTG);        // [4][NTILE]

    const int mblk = blockIdx.x;
    const int n0 = blockIdx.y * NTILE;
    const bool isW = (mblk >= 1152);
    const int tid = threadIdx.x;

    // --- A source pointers ---
    const __nv_bfloat16* Ag = nullptr;           // non-CONV
    const float* Agf = nullptr;                  // CONV
    __nv_bfloat16* Aout = nullptr;               // CONV bf16 writeback
    if constexpr (CONV) {
        Agf = isW ? (g_WTf32 + (size_t)(mblk - 1152) * 64 * X384)
                  : (Vt + ((size_t)(mblk / 6) * X384 + (mblk % 6) * 64) * X384);
        if (!isW) Aout = g_Vbf + ((size_t)(mblk / 6) * X384 + (mblk % 6) * 64) * X384;
    } else {
        Ag = isW ? (g_WTbf + (size_t)(mblk - 1152) * 64 * X384)
                 : (g_Vbf + ((size_t)(mblk / 6) * X384 + (mblk % 6) * 64) * X384);
    }

    const int ar = tid >> 3, ac = tid & 7;       // non-CONV cp.async mapping
    const int crow = tid >> 2, ccf = tid & 3;    // CONV mapping: row 0..63, col quarter

    float4 v[4];                                 // CONV fp32 staging (16 floats)

    // ---- A prologue ----
    if constexpr (CONV) {
        const float4* src = (const float4*)(Agf + crow * X384 + ccf * 16);
        #pragma unroll
        for (int q = 0; q < 4; q++) v[q] = src[q];
        unsigned pk[8];
        #pragma unroll
        for (int q = 0; q < 4; q++) {
            pk[2 * q]     = pack_bf2(v[q].x, v[q].y);
            pk[2 * q + 1] = pack_bf2(v[q].z, v[q].w);
        }
        uint4 lo = make_uint4(pk[0], pk[1], pk[2], pk[3]);
        uint4 hi = make_uint4(pk[4], pk[5], pk[6], pk[7]);
        char* slotp = As + crow * 128;
        *(uint4*)(slotp + (((2 * ccf)     ^ (crow & 7)) << 4)) = lo;
        *(uint4*)(slotp + (((2 * ccf + 1) ^ (crow & 7)) << 4)) = hi;
        if (!isW) {
            uint4* dst = (uint4*)(Aout + crow * X384 + ccf * 16);
            dst[0] = lo; dst[1] = hi;
        }
    } else {
        #pragma unroll
        for (int s = 0; s < 2; s++) {
            char* Ad = As + s * 8192;
            #pragma unroll
            for (int t = 0; t < 2; t++) {
                int r = ar + t * 32;
                cp16(Ad + r * 128 + (((ac ^ (r & 7)) << 4)), Ag + r * X384 + s * 64 + ac * 8);
            }
            // B slice for stage s folded into the same group below
            char* Bd = Bp + s * BSTG;
            for (int j = tid; j < NBCH; j += 256) {
                int n = j >> 3, c = j & 7;
                cp16(Bd + n * 128 + (((c ^ (n & 7)) << 4)),
                     g_cB + (size_t)(n0 + n) * X384 + s * 64 + c * 8);
            }
            cp_commit();
        }
    }
    if constexpr (CONV) {
        // B prologue: stages 0,1 (one group each)
        #pragma unroll
        for (int s = 0; s < 2; s++) {
            char* Bd = Bp + s * BSTG;
            for (int j = tid; j < NBCH; j += 256) {
                int n = j >> 3, c = j & 7;
                cp16(Bd + n * 128 + (((c ^ (n & 7)) << 4)),
                     g_cB + (size_t)(n0 + n) * X384 + s * 64 + c * 8);
            }
            cp_commit();
        }
    }

    const int warp = tid >> 5, lane = tid & 31;
    const int wm = warp & 3, wn = warp >> 2;     // 4 m-warps x 2 n-warps
    const int g = lane >> 2, tg = lane & 3;
    const int m0 = wm * 16;
    const int nb0 = wn * (NT * 8);

    const unsigned As_u = (unsigned)__cvta_generic_to_shared(As);
    const unsigned Bs_u = (unsigned)__cvta_generic_to_shared(Bp);

    // A ldmatrix addresses (stage-relative, one per k-step)
    const int am = m0 + (lane & 15);
    unsigned a_off[4];
    #pragma unroll
    for (int ks = 0; ks < 4; ks++) {
        int c = ks * 2 + (lane >> 4);
        a_off[ks] = (unsigned)(am * 128 + ((c ^ (am & 7)) << 4));
    }

    // B ldmatrix lane geometry (stage-relative)
    const int bmm = lane >> 3, brr = lane & 7;
    const int rowo = (bmm & 2) ? 8 : 0, kos = bmm & 1;
    unsigned b_row[NP > 0 ? NP : 1];
    unsigned b_xm[NP > 0 ? NP : 1];
    #pragma unroll
    for (int p = 0; p < (NP > 0 ? NP : 1); p++) {
        int nr = nb0 + p * 16 + rowo + brr;
        b_row[p] = (unsigned)(nr * 128);
        b_xm[p] = (unsigned)(nr & 7);
    }
    const int nr1 = nb0 + brr;                   // NT==1 (x2) path
    const unsigned b_row1 = (unsigned)(nr1 * 128), b_xm1 = (unsigned)(nr1 & 7);

    float acc[NT][4];
    #pragma unroll
    for (int nt = 0; nt < NT; nt++)
        #pragma unroll
        for (int q = 0; q < 4; q++) acc[nt][q] = 0.f;

    // ---- mainloop over 6 k-stages ----
    for (int s = 0; s < NSUB; s++) {
        if (s == NSUB - 1) cp_wait<0>(); else cp_wait<1>();
        __syncthreads();
        const int sn = s + 2;
        if (sn < NSUB) {                          // B refill slot freed by stage s-1
            char* Bd = Bp + (sn % 3) * BSTG;
            if constexpr (!CONV) {
                char* Ad = As + (sn % 3) * 8192;
                #pragma unroll
                for (int t = 0; t < 2; t++) {
                    int r = ar + t * 32;
                    cp16(Ad + r * 128 + (((ac ^ (r & 7)) << 4)), Ag + r * X384 + sn * 64 + ac * 8);
                }
            }
            for (int j = tid; j < NBCH; j += 256) {
                int n = j >> 3, c = j & 7;
                cp16(Bd + n * 128 + (((c ^ (n & 7)) << 4)),
                     g_cB + (size_t)(n0 + n) * X384 + sn * 64 + c * 8);
            }
            cp_commit();
        }

        if constexpr (CONV) {
            if (s + 1 < NSUB) {                   // issue next-stage fp32 loads early
                const float4* src = (const float4*)(Agf + crow * X384 + (s + 1) * 64 + ccf * 16);
                #pragma unroll
                for (int q = 0; q < 4; q++) v[q] = src[q];
            }
        }

        const unsigned a_stg = As_u + (CONV ? (s & 1) * 8192 : (s % 3) * 8192);
        const unsigned b_stg = Bs_u + (s % 3) * BSTG;

        #pragma unroll
        for (int ks = 0; ks < 4; ks++) {
            unsigned a[4];
            ldmx4(a, a_stg + a_off[ks]);
            const unsigned c = (unsigned)(ks * 2 + kos);
            if constexpr (NP > 0) {
                #pragma unroll
                for (int p = 0; p < NP; p++) {
                    unsigned bb[4];
                    ldmx4(bb, b_stg + b_row[p] + ((c ^ b_xm[p]) << 4));
                    mma16816(acc[2 * p],     a, bb[0], bb[1]);
                    mma16816(acc[2 * p + 1], a, bb[2], bb[3]);
                }
            } else {
                unsigned bb[2];
                ldmx2(bb, b_stg + b_row1 + ((c ^ b_xm1) << 4));
                mma16816(acc[0], a, bb[0], bb[1]);
            }
        }

        if constexpr (CONV) {
            if (s + 1 < NSUB) {                   // convert + STS into freed slot + STG
                unsigned pk[8];
                #pragma unroll
                for (int q = 0; q < 4; q++) {
                    pk[2 * q]     = pack_bf2(v[q].x, v[q].y);
                    pk[2 * q + 1] = pack_bf2(v[q].z, v[q].w);
                }
                uint4 lo = make_uint4(pk[0], pk[1], pk[2], pk[3]);
                uint4 hi = make_uint4(pk[4], pk[5], pk[6], pk[7]);
                char* slotp = As + ((s + 1) & 1) * 8192 + crow * 128;
                *(uint4*)(slotp + (((2 * ccf)     ^ (crow & 7)) << 4)) = lo;
                *(uint4*)(slotp + (((2 * ccf + 1) ^ (crow & 7)) << 4)) = hi;
                if (!isW) {
                    uint4* dst = (uint4*)(Aout + crow * X384 + (s + 1) * 64 + ccf * 16);
                    dst[0] = lo; dst[1] = hi;
                }
            }
        }
    }

    if (!isW) {
        const int xb = mblk % 6, hh = mblk / 6;
        const int xf = xb * 64 + m0 + g;          // global x for this thread's rows
        #pragma unroll
        for (int nt = 0; nt < NT; nt++) {
            int nl = nb0 + nt * 8 + 2 * tg;       // local n
            const __nv_bfloat16* c0p = g_cB + (size_t)(n0 + nl) * X384 + xf;
            const __nv_bfloat16* c1p = c0p + X384;
            float p0 = __bfloat162float(c0p[0]) * acc[nt][0]
                     + __bfloat162float(c0p[8]) * acc[nt][2];
            float p1 = __bfloat162float(c1p[0]) * acc[nt][1]
                     + __bfloat162float(c1p[8]) * acc[nt][3];
            #pragma unroll
            for (int sh = 4; sh < 32; sh <<= 1) { // reduce over g
                p0 += __shfl_xor_sync(0xffffffffu, p0, sh);
                p1 += __shfl_xor_sync(0xffffffffu, p1, sh);
            }
            if (g == 0) {
                ysm[wm * NTILE + nl] = p0;
                ysm[wm * NTILE + nl + 1] = p1;
            }
        }
        __syncthreads();
        for (int n = tid; n < NTILE; n += 256) {
            float vv = ysm[n] + ysm[NTILE + n] + ysm[2 * NTILE + n] + ysm[3 * NTILE + n];
            g_part[xb][hh][n0 + n] = vv;
        }
    } else {
        const int hb = (mblk - 1152) * 64;
        int hh = hb + m0 + g;
        #pragma unroll
        for (int nt = 0; nt < NT; nt++) {
            int n = n0 + nb0 + nt * 8 + 2 * tg;
            if (hh < H) {
                g_part[6][hh][n]     = acc[nt][0];
                g_part[6][hh][n + 1] = acc[nt][1];
            }
            if (hh + 8 < H) {
                g_part[6][hh + 8][n]     = acc[nt][2];
                g_part[6][hh + 8][n + 1] = acc[nt][3];
            }
        }
    }
}

// ---------------------------------------------------------------------------
// Finalize: sum partials + bias, tanh, write node + next level's B row.
// ---------------------------------------------------------------------------
__global__ void finalize_kernel(int outBase, int Nout, int hasNext,
                                const float* __restrict__ bias) {
    int n = blockIdx.x, h = threadIdx.x;
    float v = bias[h];
    #pragma unroll
    for (int i = 0; i < 7; i++) v += g_part[i][h][n];
    v = tanhf(v);
    g_nodes[(size_t)(outBase + n) * H + h] = v;
    if (hasNext) {
        int npt = Nout >> 3;
        int bt = n / npt, j = n - bt * npt;
        int m = bt * (npt >> 1) + (j >> 1);
        g_cB[m * X384 + (j & 1) * H + h] = __float2bfloat16_rn(v);
    }
}

// ---------------------------------------------------------------------------
// Logits + log_softmax, one warp per node
// ---------------------------------------------------------------------------
__global__ void logits_kernel(const float* __restrict__ Wout_w,
                              const float* __restrict__ Wout_b,
                              float* __restrict__ out) {
    int node = (blockIdx.x * blockDim.x + threadIdx.x) >> 5;   // 63 * 8 = 504
    int lane = threadIdx.x & 31;
    const float* v = g_nodes + (size_t)node * H;
    float l[5];
    #pragma unroll
    for (int o = 0; o < 5; o++) {
        float p = 0.f;
        #pragma unroll
        for (int i = 0; i < 6; i++) {
            int idx = lane + 32 * i;
            p += v[idx] * Wout_w[o * H + idx];
        }
        #pragma unroll
        for (int s = 16; s; s >>= 1) p += __shfl_xor_sync(0xffffffffu, p, s);
        l[o] = p + Wout_b[o];
    }
    if (lane == 0) {
        float m = l[0];
        #pragma unroll
        for (int o = 1; o < 5; o++) m = fmaxf(m, l[o]);
        float s = 0.f;
        #pragma unroll
        for (int o = 0; o < 5; o++) s += expf(l[o] - m);
        float ls = logf(s);
        #pragma unroll
        for (int o = 0; o < 5; o++) out[node * 5 + o] = l[o] - m - ls;
    }
}

// ---------------------------------------------------------------------------
static inline size_t smem_bytes(int NTILE, bool conv) {
    return (size_t)(conv ? 2 : 3) * 8192 + (size_t)3 * NTILE * 128 + (size_t)4 * NTILE * 4;
}

extern "C" void kernel_launch(void* const* d_in, const int* in_sizes, int n_in,
                              void* d_out, int out_size) {
    const float* embed  = (const float*)d_in[0];
    const float* Vt     = (const float*)d_in[1];
    const float* W      = (const float*)d_in[2];
    const float* b      = (const float*)d_in[3];
    const float* Wout_w = (const float*)d_in[4];
    const float* Wout_b = (const float*)d_in[5];
    const int*   leaf   = (const int*)d_in[6];
    float* out = (float*)d_out;

    static bool attr_set = false;
    if (!attr_set) {
        cudaFuncSetAttribute(gemm_level<128, true>, cudaFuncAttributeMaxDynamicSharedMemorySize, (int)smem_bytes(128, true));
        cudaFuncSetAttribute(gemm_level<64, false>, cudaFuncAttributeMaxDynamicSharedMemorySize, (int)smem_bytes(64, false));
        cudaFuncSetAttribute(gemm_level<32, false>, cudaFuncAttributeMaxDynamicSharedMemorySize, (int)smem_bytes(32, false));
        cudaFuncSetAttribute(gemm_level<16, false>, cudaFuncAttributeMaxDynamicSharedMemorySize, (int)smem_bytes(16, false));
        attr_set = true;
    }

    convertWT_kernel<<<256, 128>>>(W);
    leaf_kernel<<<256, H>>>(embed, leaf);   // also builds level-0 B

    // level 0: reads V fp32, converts+writes g_Vbf, computes 256 leaves -> 128 nodes
    gemm_level<128, true><<<dim3(1156, 1), 256, smem_bytes(128, true)>>>(Vt);
    finalize_kernel<<<128, H>>>(256, 128, 1, b);
    // level 1: 128 -> 64
    gemm_level<64, false><<<dim3(1156, 1), 256, smem_bytes(64, false)>>>(Vt);
    finalize_kernel<<<64, H>>>(384, 64, 1, b);
    // level 2: 64 -> 32
    gemm_level<32, false><<<dim3(1156, 1), 256, smem_bytes(32, false)>>>(Vt);
    finalize_kernel<<<32, H>>>(448, 32, 1, b);
    // level 3: 32 -> 16
    gemm_level<16, false><<<dim3(1156, 1), 256, smem_bytes(16, false)>>>(Vt);
    finalize_kernel<<<16, H>>>(480, 16, 1, b);
    // level 4: 16 -> 8 (B rows 8..15 stale but feed only unused columns)
    gemm_level<16, false><<<dim3(1156, 1), 256, smem_bytes(16, false)>>>(Vt);
    finalize_kernel<<<8, H>>>(496, 8, 0, b);

    logits_kernel<<<63, 256>>>(Wout_w, Wout_b, out);
}